// round 14
// baseline (speedup 1.0000x reference)
#include <cuda_runtime.h>
#include <cuda_fp16.h>
#include <cstdint>

#define OUT_F   11008
#define IN_F    4096
#define TOK     16
#define TILE_M  128
#define NTILE   (OUT_F / TILE_M)   // 86
#define KSPLIT  32
#define KCHUNK  (IN_F / KSPLIT)    // 128
#define THREADS 256
#define NCTA    592                // 148 SMs x 4 co-resident CTAs
#define NITEMS  (NTILE * KSPLIT)   // 2752
#define XROW    (KCHUNK * 2 + 16)  // 272 B padded row
#define YSROW   132                // floats; bank-conflict-free stage tile

__device__ unsigned int g_ticket;
__device__ unsigned int g_done;
__device__ unsigned int g_tflag[NTILE];

// ---------------- helpers ----------------
__device__ __forceinline__ uint32_t smem_u32(const void* p) {
    uint32_t a;
    asm("{ .reg .u64 t; cvta.to.shared.u64 t, %1; cvt.u32.u64 %0, t; }" : "=r"(a) : "l"(p));
    return a;
}
__device__ __forceinline__ unsigned long long pack2(unsigned int lo, unsigned int hi) {
    unsigned long long d; asm("mov.b64 %0, {%1,%2};" : "=l"(d) : "r"(lo), "r"(hi)); return d;
}
__device__ __forceinline__ unsigned long long add2(unsigned long long a, unsigned long long b) {
    unsigned long long d; asm("add.rn.f32x2 %0, %1, %2;" : "=l"(d) : "l"(a), "l"(b)); return d;
}
__device__ __forceinline__ unsigned long long mul2(unsigned long long a, unsigned long long b) {
    unsigned long long d; asm("mul.rn.f32x2 %0, %1, %2;" : "=l"(d) : "l"(a), "l"(b)); return d;
}
// q0,q1 in [0,15] -> fp16x2 {s*(q0-8), s*(q1-8)}; fp32-exact dequant, one fp16 round.
__device__ __forceinline__ uint32_t dqh(int q0, int q1, unsigned long long s2) {
    const unsigned long long M2 = pack2(0xCB000008u, 0xCB000008u); // -8388616.0f x2
    unsigned long long f = pack2(0x4B000000u | (unsigned)q0, 0x4B000000u | (unsigned)q1);
    unsigned long long w = mul2(add2(f, M2), s2);
    unsigned int l, h;
    asm("mov.b64 {%0,%1}, %2;" : "=r"(l), "=r"(h) : "l"(w));
    uint32_t r;
    asm("cvt.rn.f16x2.f32 %0, %1, %2;" : "=r"(r)
        : "f"(__uint_as_float(h)), "f"(__uint_as_float(l)));
    return r;
}
__device__ __forceinline__ void mma16816(float* c, uint32_t a0, uint32_t a1,
                                         uint32_t a2, uint32_t a3,
                                         uint32_t b0, uint32_t b1) {
    asm volatile(
        "mma.sync.aligned.m16n8k16.row.col.f32.f16.f16.f32 "
        "{%0,%1,%2,%3}, {%4,%5,%6,%7}, {%8,%9}, {%0,%1,%2,%3};"
        : "+f"(c[0]), "+f"(c[1]), "+f"(c[2]), "+f"(c[3])
        : "r"(a0), "r"(a1), "r"(a2), "r"(a3), "r"(b0), "r"(b1));
}

// k permutation within a 64-k step: c=(j,p) uses k = 64s + 32j + 8t + 4p + {0..3}
__device__ __forceinline__ void step_body(
    int s, bool pf,
    const int4 (&curA)[4], const int4 (&curB)[4],
    int4 (&nxtA)[4], int4 (&nxtB)[4],
    const int4* qA, const int4* qB,
    float2 scA, float2 scB,
    uint32_t xb0, uint32_t xb1,
    float (&acc)[2][4])
{
    if (pf) {
        // prefetch step-1 A: 8 LDG.128, evict-first (streaming, zero reuse)
        #pragma unroll
        for (int j2 = 0; j2 < 4; j2++) {
            int idx = 16 + (j2 >> 1) * 8 + (j2 & 1);
            nxtA[j2] = __ldcs(qA + idx);
            nxtB[j2] = __ldcs(qB + idx);
        }
    }

    // B fragments: 4x LDS.128 from fp16 x tile
    uint4 bh[2][2];
    #pragma unroll
    for (int j = 0; j < 2; j++) {
        asm volatile("ld.shared.v4.b32 {%0,%1,%2,%3}, [%4];"
            : "=r"(bh[0][j].x), "=r"(bh[0][j].y), "=r"(bh[0][j].z), "=r"(bh[0][j].w)
            : "r"(xb0 + (uint32_t)(s * 128 + 64 * j)));
        asm volatile("ld.shared.v4.b32 {%0,%1,%2,%3}, [%4];"
            : "=r"(bh[1][j].x), "=r"(bh[1][j].y), "=r"(bh[1][j].z), "=r"(bh[1][j].w)
            : "r"(xb1 + (uint32_t)(s * 128 + 64 * j)));
    }

    #pragma unroll
    for (int j = 0; j < 2; j++) {
        float sa = j ? scA.y : scA.x;
        float sb = j ? scB.y : scB.x;
        unsigned long long s2a = pack2(__float_as_uint(sa), __float_as_uint(sa));
        unsigned long long s2b = pack2(__float_as_uint(sb), __float_as_uint(sb));
        #pragma unroll
        for (int p = 0; p < 2; p++) {
            int4 va = curA[2 * j + p], vb = curB[2 * j + p];
            uint32_t a0 = dqh(va.x, va.y, s2a);
            uint32_t a2 = dqh(va.z, va.w, s2a);
            uint32_t a1 = dqh(vb.x, vb.y, s2b);
            uint32_t a3 = dqh(vb.z, vb.w, s2b);
            const uint32_t* b0 = reinterpret_cast<const uint32_t*>(&bh[0][j]);
            const uint32_t* b1 = reinterpret_cast<const uint32_t*>(&bh[1][j]);
            mma16816(acc[0], a0, a1, a2, a3, b0[2 * p], b0[2 * p + 1]);
            mma16816(acc[1], a0, a1, a2, a3, b1[2 * p], b1[2 * p + 1]);
        }
    }
}

__global__ void __launch_bounds__(THREADS, 4)
qmma(const float* __restrict__ x, const int* __restrict__ qw,
     const float* __restrict__ scales, const float* __restrict__ bias,
     float* __restrict__ y)
{
    __shared__ __align__(16) char  xs[TOK * XROW];   // 4.25 KB fp16 x tile
    __shared__ __align__(16) float ys[TOK * YSROW];  // 8.25 KB result stage
    __shared__ int sh_item;
    const uint32_t sb = smem_u32(xs);

    const int tid = threadIdx.x;
    const int lane = tid & 31, wid = tid >> 5;
    const int g = lane >> 2, t = lane & 3;
    const int rowoff = wid * 16 + g;

    const uint32_t xb0 = sb + (uint32_t)(g * XROW + 16 * t);         // tokens 0..7
    const uint32_t xb1 = sb + (uint32_t)((g + 8) * XROW + 16 * t);   // tokens 8..15

    for (;;) {
        if (tid == 0) sh_item = (int)atomicAdd(&g_ticket, 1u);
        __syncthreads();                 // publish item; fences prev ys reads
        const int itm = sh_item;
        if (itm >= NITEMS) break;

        const int tile = itm >> 5;
        const int out0 = tile * TILE_M;
        const int k0   = (itm & 31) * KCHUNK;
        const int rowA = out0 + rowoff, rowB = rowA + 8;

        const int4* qA = reinterpret_cast<const int4*>(qw + (size_t)rowA * IN_F + k0) + 2 * t;
        const int4* qB = reinterpret_cast<const int4*>(qw + (size_t)rowB * IN_F + k0) + 2 * t;
        const float2* sA = reinterpret_cast<const float2*>(scales + (size_t)rowA * (IN_F / 32) + k0 / 32);
        const float2* sB = reinterpret_cast<const float2*>(scales + (size_t)rowB * (IN_F / 32) + k0 / 32);

        float acc[2][4] = {};
        int4 b0A[4], b0B[4], b1A[4], b1B[4];

        // start the qweight DRAM stream immediately
        #pragma unroll
        for (int j2 = 0; j2 < 4; j2++) {
            int idx = (j2 >> 1) * 8 + (j2 & 1);
            b0A[j2] = __ldcs(qA + idx);
            b0B[j2] = __ldcs(qB + idx);
        }
        float2 scA0 = __ldg(sA + 0), scA1 = __ldg(sA + 1);
        float2 scB0 = __ldg(sB + 0), scB1 = __ldg(sB + 1);

        // x conversion: this item's 16x128 fp32 slice -> fp16 smem
        #pragma unroll
        for (int it = 0; it < 2; it++) {
            int i = tid + it * THREADS;
            int tok = i >> 5, kq = i & 31;
            float4 v = __ldg(reinterpret_cast<const float4*>(x + (size_t)tok * IN_F + k0) + kq);
            uint32_t h01, h23;
            asm("cvt.rn.f16x2.f32 %0, %1, %2;" : "=r"(h01) : "f"(v.y), "f"(v.x));
            asm("cvt.rn.f16x2.f32 %0, %1, %2;" : "=r"(h23) : "f"(v.w), "f"(v.z));
            asm volatile("st.shared.v2.b32 [%0], {%1,%2};"
                         :: "r"(sb + (uint32_t)(tok * XROW + kq * 8)), "r"(h01), "r"(h23) : "memory");
        }
        __syncthreads();

        // two steps of 64 k; no dead tail prefetch
        step_body(0, true,  b0A, b0B, b1A, b1B, qA, qB, scA0, scB0, xb0, xb1, acc);
        step_body(1, false, b1A, b1B, b0A, b0B, qA, qB, scA1, scB1, xb0, xb1, acc);

        // ---- stage 16x128 tile in smem ----
        {
            const int tk = 2 * t;
            ys[(tk    ) * YSROW + rowoff    ] = acc[0][0];
            ys[(tk + 1) * YSROW + rowoff    ] = acc[0][1];
            ys[(tk    ) * YSROW + rowoff + 8] = acc[0][2];
            ys[(tk + 1) * YSROW + rowoff + 8] = acc[0][3];
            ys[(tk + 8) * YSROW + rowoff    ] = acc[1][0];
            ys[(tk + 9) * YSROW + rowoff    ] = acc[1][1];
            ys[(tk + 8) * YSROW + rowoff + 8] = acc[1][2];
            ys[(tk + 9) * YSROW + rowoff + 8] = acc[1][3];
        }

        const bool k0item = ((itm & 31) == 0);
        if (!k0item && tid == 0) {
            // acquire tile's bias-init flag (set by the k0 item's CTA)
            while (atomicAdd(&g_tflag[tile], 0u) == 0u) __nanosleep(32);
            __threadfence();
        }
        __syncthreads();                 // ys complete + flag observed

        if (k0item) {
            // initialize y = bias + partial with plain stores, then release flag
            #pragma unroll
            for (int i = 0; i < 2; i++) {
                int idx = tid + i * THREADS;
                int tok = idx >> 5, o4 = idx & 31;
                float4 v = *reinterpret_cast<const float4*>(&ys[tok * YSROW + o4 * 4]);
                float4 b = __ldg(reinterpret_cast<const float4*>(bias) + (out0 >> 2) + o4);
                float4 r = make_float4(v.x + b.x, v.y + b.y, v.z + b.z, v.w + b.w);
                *reinterpret_cast<float4*>(y + (size_t)tok * OUT_F + out0 + o4 * 4) = r;
            }
            __threadfence();
            __syncthreads();
            if (tid == 0) atomicExch(&g_tflag[tile], 1u);
        } else {
            #pragma unroll
            for (int i = 0; i < 2; i++) {
                int idx = tid + i * THREADS;
                int tok = idx >> 5, o4 = idx & 31;
                float4 v = *reinterpret_cast<const float4*>(&ys[tok * YSROW + o4 * 4]);
                float* dst = y + (size_t)tok * OUT_F + out0 + o4 * 4;
                asm volatile("red.global.add.v4.f32 [%0], {%1,%2,%3,%4};"
                             :: "l"(dst), "f"(v.x), "f"(v.y), "f"(v.z), "f"(v.w) : "memory");
            }
        }
    }

    // ---- self-reset for the next (graph-replayed) call ----
    if (tid == 0) {
        if (atomicAdd(&g_done, 1u) == NCTA - 1) {
            for (int i = 0; i < NTILE; i++) g_tflag[i] = 0u;
            g_done = 0u;
            g_ticket = 0u;
            __threadfence();
        }
    }
}

extern "C" void kernel_launch(void* const* d_in, const int* in_sizes, int n_in,
                              void* d_out, int out_size)
{
    const float* x      = (const float*)d_in[0];
    const int*   qw     = (const int*)d_in[1];
    const float* scales = (const float*)d_in[2];
    const float* bias   = (const float*)d_in[3];
    float*       y      = (float*)d_out;

    qmma<<<NCTA, THREADS>>>(x, qw, scales, bias, y);
}

// round 17
// speedup vs baseline: 1.2325x; 1.2325x over previous
#include <cuda_runtime.h>
#include <cuda_fp16.h>
#include <cstdint>

#define OUT_F   11008
#define IN_F    4096
#define TOK     16
#define TILE_M  128
#define NTILE   (OUT_F / TILE_M)   // 86
#define KSPLIT  32
#define KCHUNK  (IN_F / KSPLIT)    // 128
#define THREADS 256
#define NCTA    592                // 148 SMs x 4 co-resident CTAs
#define NITEMS  (NTILE * KSPLIT)   // 2752
#define XROW    (KCHUNK * 2 + 16)  // 272 B padded row
#define YSROW   132                // floats; bank-conflict-free stage tile

__device__ unsigned int g_ticket = NCTA;   // self-managed; reset to NCTA at exit
__device__ unsigned int g_done   = 0;

// ---------------- helpers ----------------
__device__ __forceinline__ uint32_t smem_u32(const void* p) {
    uint32_t a;
    asm("{ .reg .u64 t; cvta.to.shared.u64 t, %1; cvt.u32.u64 %0, t; }" : "=r"(a) : "l"(p));
    return a;
}
__device__ __forceinline__ unsigned long long pack2(unsigned int lo, unsigned int hi) {
    unsigned long long d; asm("mov.b64 %0, {%1,%2};" : "=l"(d) : "r"(lo), "r"(hi)); return d;
}
__device__ __forceinline__ unsigned long long add2(unsigned long long a, unsigned long long b) {
    unsigned long long d; asm("add.rn.f32x2 %0, %1, %2;" : "=l"(d) : "l"(a), "l"(b)); return d;
}
__device__ __forceinline__ unsigned long long mul2(unsigned long long a, unsigned long long b) {
    unsigned long long d; asm("mul.rn.f32x2 %0, %1, %2;" : "=l"(d) : "l"(a), "l"(b)); return d;
}
// q0,q1 in [0,15] -> fp16x2 {s*(q0-8), s*(q1-8)}; fp32-exact dequant, one fp16 round.
__device__ __forceinline__ uint32_t dqh(int q0, int q1, unsigned long long s2) {
    const unsigned long long M2 = pack2(0xCB000008u, 0xCB000008u); // -8388616.0f x2
    unsigned long long f = pack2(0x4B000000u | (unsigned)q0, 0x4B000000u | (unsigned)q1);
    unsigned long long w = mul2(add2(f, M2), s2);
    unsigned int l, h;
    asm("mov.b64 {%0,%1}, %2;" : "=r"(l), "=r"(h) : "l"(w));
    uint32_t r;
    asm("cvt.rn.f16x2.f32 %0, %1, %2;" : "=r"(r)
        : "f"(__uint_as_float(h)), "f"(__uint_as_float(l)));
    return r;
}
__device__ __forceinline__ void mma16816(float* c, uint32_t a0, uint32_t a1,
                                         uint32_t a2, uint32_t a3,
                                         uint32_t b0, uint32_t b1) {
    asm volatile(
        "mma.sync.aligned.m16n8k16.row.col.f32.f16.f16.f32 "
        "{%0,%1,%2,%3}, {%4,%5,%6,%7}, {%8,%9}, {%0,%1,%2,%3};"
        : "+f"(c[0]), "+f"(c[1]), "+f"(c[2]), "+f"(c[3])
        : "r"(a0), "r"(a1), "r"(a2), "r"(a3), "r"(b0), "r"(b1));
}

// ---------------- kernel 1: y = bias (PDL primary) ----------------
__global__ void yinit(const float* __restrict__ bias, float* __restrict__ y)
{
    cudaTriggerProgrammaticLaunchCompletion();   // let qmma launch concurrently
    int i = blockIdx.x * 256 + threadIdx.x;      // float4 idx, 44032 total
    int tok = i / (OUT_F / 4);
    int o4  = i - tok * (OUT_F / 4);
    float4 b = __ldg(reinterpret_cast<const float4*>(bias) + o4);
    reinterpret_cast<float4*>(y)[i] = b;
}

// ---------------- kernel 2: persistent quantized GEMM (round-8 core) ---------
// k permutation within a 64-k step: c=(j,p) uses k = 64s + 32j + 8t + 4p + {0..3}
__device__ __forceinline__ void step_body(
    int s, bool pf,
    const int4 (&curA)[4], const int4 (&curB)[4],
    int4 (&nxtA)[4], int4 (&nxtB)[4],
    const int4* qA, const int4* qB,
    float2 scA, float2 scB,
    uint32_t xb0, uint32_t xb1,
    float (&acc)[2][4])
{
    if (pf) {
        // prefetch step-1 A: 8 LDG.128, evict-first (streaming, zero reuse)
        #pragma unroll
        for (int j2 = 0; j2 < 4; j2++) {
            int idx = 16 + (j2 >> 1) * 8 + (j2 & 1);
            nxtA[j2] = __ldcs(qA + idx);
            nxtB[j2] = __ldcs(qB + idx);
        }
    }

    // B fragments: 4x LDS.128 from fp16 x tile
    uint4 bh[2][2];
    #pragma unroll
    for (int j = 0; j < 2; j++) {
        asm volatile("ld.shared.v4.b32 {%0,%1,%2,%3}, [%4];"
            : "=r"(bh[0][j].x), "=r"(bh[0][j].y), "=r"(bh[0][j].z), "=r"(bh[0][j].w)
            : "r"(xb0 + (uint32_t)(s * 128 + 64 * j)));
        asm volatile("ld.shared.v4.b32 {%0,%1,%2,%3}, [%4];"
            : "=r"(bh[1][j].x), "=r"(bh[1][j].y), "=r"(bh[1][j].z), "=r"(bh[1][j].w)
            : "r"(xb1 + (uint32_t)(s * 128 + 64 * j)));
    }

    #pragma unroll
    for (int j = 0; j < 2; j++) {
        float sa = j ? scA.y : scA.x;
        float sb = j ? scB.y : scB.x;
        unsigned long long s2a = pack2(__float_as_uint(sa), __float_as_uint(sa));
        unsigned long long s2b = pack2(__float_as_uint(sb), __float_as_uint(sb));
        #pragma unroll
        for (int p = 0; p < 2; p++) {
            int4 va = curA[2 * j + p], vb = curB[2 * j + p];
            uint32_t a0 = dqh(va.x, va.y, s2a);
            uint32_t a2 = dqh(va.z, va.w, s2a);
            uint32_t a1 = dqh(vb.x, vb.y, s2b);
            uint32_t a3 = dqh(vb.z, vb.w, s2b);
            const uint32_t* b0 = reinterpret_cast<const uint32_t*>(&bh[0][j]);
            const uint32_t* b1 = reinterpret_cast<const uint32_t*>(&bh[1][j]);
            mma16816(acc[0], a0, a1, a2, a3, b0[2 * p], b0[2 * p + 1]);
            mma16816(acc[1], a0, a1, a2, a3, b1[2 * p], b1[2 * p + 1]);
        }
    }
}

__global__ void __launch_bounds__(THREADS, 4)
qmma(const float* __restrict__ x, const int* __restrict__ qw,
     const float* __restrict__ scales, float* __restrict__ y)
{
    __shared__ __align__(16) char  xs[TOK * XROW];   // 4.25 KB fp16 x tile
    __shared__ __align__(16) float ys[TOK * YSROW];  // 8.25 KB result stage
    __shared__ int sh_next;
    const uint32_t sb = smem_u32(xs);

    const int tid = threadIdx.x;
    const int lane = tid & 31, wid = tid >> 5;
    const int g = lane >> 2, t = lane & 3;
    const int rowoff = wid * 16 + g;

    const uint32_t xb0 = sb + (uint32_t)(g * XROW + 16 * t);         // tokens 0..7
    const uint32_t xb1 = sb + (uint32_t)((g + 8) * XROW + 16 * t);   // tokens 8..15

    int itm = blockIdx.x;                // first item; ticket starts at NCTA
    bool dep_synced = false;

    for (;;) {
        const int out0 = (itm >> 5) * TILE_M;
        const int k0   = (itm & 31) * KCHUNK;
        const int rowA = out0 + rowoff, rowB = rowA + 8;

        const int4* qA = reinterpret_cast<const int4*>(qw + (size_t)rowA * IN_F + k0) + 2 * t;
        const int4* qB = reinterpret_cast<const int4*>(qw + (size_t)rowB * IN_F + k0) + 2 * t;
        const float2* sA = reinterpret_cast<const float2*>(scales + (size_t)rowA * (IN_F / 32) + k0 / 32);
        const float2* sB = reinterpret_cast<const float2*>(scales + (size_t)rowB * (IN_F / 32) + k0 / 32);

        float acc[2][4] = {};
        int4 b0A[4], b0B[4], b1A[4], b1B[4];

        // start the qweight DRAM stream immediately
        #pragma unroll
        for (int j2 = 0; j2 < 4; j2++) {
            int idx = (j2 >> 1) * 8 + (j2 & 1);
            b0A[j2] = __ldcs(qA + idx);
            b0B[j2] = __ldcs(qB + idx);
        }
        float2 scA0 = __ldg(sA + 0), scA1 = __ldg(sA + 1);
        float2 scB0 = __ldg(sB + 0), scB1 = __ldg(sB + 1);

        // fetch next ticket during compute (published by the xs barrier chain)
        if (tid == 0) sh_next = (int)atomicAdd(&g_ticket, 1u);

        // x conversion: this item's 16x128 fp32 slice -> fp16 smem
        #pragma unroll
        for (int it = 0; it < 2; it++) {
            int i = tid + it * THREADS;
            int tok = i >> 5, kq = i & 31;
            float4 v = __ldg(reinterpret_cast<const float4*>(x + (size_t)tok * IN_F + k0) + kq);
            uint32_t h01, h23;
            asm("cvt.rn.f16x2.f32 %0, %1, %2;" : "=r"(h01) : "f"(v.y), "f"(v.x));
            asm("cvt.rn.f16x2.f32 %0, %1, %2;" : "=r"(h23) : "f"(v.w), "f"(v.z));
            asm volatile("st.shared.v2.b32 [%0], {%1,%2};"
                         :: "r"(sb + (uint32_t)(tok * XROW + kq * 8)), "r"(h01), "r"(h23) : "memory");
        }
        __syncthreads();                 // xs ready

        // two steps of 64 k; no dead tail prefetch
        step_body(0, true,  b0A, b0B, b1A, b1B, qA, qB, scA0, scB0, xb0, xb1, acc);
        step_body(1, false, b1A, b1B, b0A, b0B, qA, qB, scA1, scB1, xb0, xb1, acc);

        // ---- epilogue: stage 16x128 tile in smem, then coalesced vector reds ----
        {
            const int tk = 2 * t;
            ys[(tk    ) * YSROW + rowoff    ] = acc[0][0];
            ys[(tk + 1) * YSROW + rowoff    ] = acc[0][1];
            ys[(tk    ) * YSROW + rowoff + 8] = acc[0][2];
            ys[(tk + 1) * YSROW + rowoff + 8] = acc[0][3];
            ys[(tk + 8) * YSROW + rowoff    ] = acc[1][0];
            ys[(tk + 9) * YSROW + rowoff    ] = acc[1][1];
            ys[(tk + 8) * YSROW + rowoff + 8] = acc[1][2];
            ys[(tk + 9) * YSROW + rowoff + 8] = acc[1][3];
        }
        __syncthreads();                 // ys complete + sh_next published

        const int nitm = sh_next;

        // before the FIRST y write: wait for yinit (overlapped so far via PDL)
        if (!dep_synced) {
            cudaGridDependencySynchronize();
            dep_synced = true;
        }

        #pragma unroll
        for (int i = 0; i < 2; i++) {
            int idx = tid + i * THREADS;         // 0..511
            int tok = idx >> 5, o4 = idx & 31;
            float4 v = *reinterpret_cast<const float4*>(&ys[tok * YSROW + o4 * 4]);
            float* dst = y + (size_t)tok * OUT_F + out0 + o4 * 4;
            asm volatile("red.global.add.v4.f32 [%0], {%1,%2,%3,%4};"
                         :: "l"(dst), "f"(v.x), "f"(v.y), "f"(v.z), "f"(v.w) : "memory");
        }
        if (nitm >= NITEMS) break;
        itm = nitm;
        __syncthreads();                 // reds done before ys/xs overwritten
    }

    // ---- self-reset for the next (graph-replayed) call ----
    if (tid == 0) {
        if (atomicAdd(&g_done, 1u) == NCTA - 1) {
            g_done = 0u;
            g_ticket = NCTA;
            __threadfence();
        }
    }
}

extern "C" void kernel_launch(void* const* d_in, const int* in_sizes, int n_in,
                              void* d_out, int out_size)
{
    const float* x      = (const float*)d_in[0];
    const int*   qw     = (const int*)d_in[1];
    const float* scales = (const float*)d_in[2];
    const float* bias   = (const float*)d_in[3];
    float*       y      = (float*)d_out;

    yinit<<<TOK * OUT_F / 4 / 256, 256>>>(bias, y);

    cudaLaunchAttribute attrs[1];
    attrs[0].id = cudaLaunchAttributeProgrammaticStreamSerialization;
    attrs[0].val.programmaticStreamSerializationAllowed = 1;

    cudaLaunchConfig_t cfg = {};
    cfg.gridDim  = dim3(NCTA, 1, 1);
    cfg.blockDim = dim3(THREADS, 1, 1);
    cfg.dynamicSmemBytes = 0;
    cfg.stream = 0;
    cfg.attrs = attrs;
    cfg.numAttrs = 1;
    cudaLaunchKernelEx(&cfg, qmma, x, qw, scales, y);
}